// round 12
// baseline (speedup 1.0000x reference)
#include <cuda_runtime.h>
#include <cstdint>

// Problem-fixed maxima (N=100000, E=3200000 per reference setup_inputs).
#define MAXN 100000
#define MAXE 3200000
#define NB1 ((MAXN + 255) / 256)   // 391 scan blocks

// Scratch (allocation-free contract: __device__ globals).
__device__ int g_cnt[MAXN];                       // in-degree (excluding self-loop)
__device__ int g_row[MAXN];                       // CSR row start (exclusive prefix sum)
__device__ int g_cur[MAXN];                       // placement cursor
__device__ int g_bsum[512];                       // scan block sums
__device__ int g_boff[512];                       // scan block offsets
__device__ int g_csr[MAXE];                       // src indices grouped by dst
__device__ __align__(16) float g_xs[MAXN * 4];    // x * dinv  (source-scaled payload)
__device__ __align__(16) float g_t2s[MAXN * 4];   // t2 * dinv (source-scaled payload)

// 1) zero the degree histogram
__global__ void k_zero(int n) {
    int i = blockIdx.x * blockDim.x + threadIdx.x;
    if (i < n) g_cnt[i] = 0;
}

// 2) in-degree histogram, 4 edges/thread via int4
__global__ void k_count(const int* __restrict__ edge_index, int E) {
    int i = blockIdx.x * blockDim.x + threadIdx.x;
    int e0 = i * 4;
    if (e0 >= E) return;
    const int* dstp = edge_index + E;
    if (e0 + 3 < E) {
        int4 d4 = *reinterpret_cast<const int4*>(dstp + e0);
        atomicAdd(&g_cnt[d4.x], 1);
        atomicAdd(&g_cnt[d4.y], 1);
        atomicAdd(&g_cnt[d4.z], 1);
        atomicAdd(&g_cnt[d4.w], 1);
    } else {
        for (int e = e0; e < E; e++) atomicAdd(&g_cnt[dstp[e]], 1);
    }
}

// 3a) per-block exclusive scan (256 elems/block) + block totals
__global__ void k_scan1(int n) {
    __shared__ int sh[256];
    int i = blockIdx.x * 256 + threadIdx.x;
    int v = (i < n) ? g_cnt[i] : 0;
    sh[threadIdx.x] = v;
    __syncthreads();
#pragma unroll
    for (int off = 1; off < 256; off <<= 1) {
        int t = (threadIdx.x >= off) ? sh[threadIdx.x - off] : 0;
        __syncthreads();
        sh[threadIdx.x] += t;
        __syncthreads();
    }
    if (i < n) g_row[i] = sh[threadIdx.x] - v;   // exclusive
    if (threadIdx.x == 255) g_bsum[blockIdx.x] = sh[255];
}

// 3b) single-block exclusive scan of the block totals
__global__ void k_scan2(int nb) {
    __shared__ int sh[512];
    int t = threadIdx.x;
    int v = (t < nb) ? g_bsum[t] : 0;
    sh[t] = v;
    __syncthreads();
#pragma unroll
    for (int off = 1; off < 512; off <<= 1) {
        int u = (t >= off) ? sh[t - off] : 0;
        __syncthreads();
        sh[t] += u;
        __syncthreads();
    }
    if (t < nb) g_boff[t] = sh[t] - v;
}

// 3c) add block offsets; init cursors
__global__ void k_scan3(int n) {
    int i = blockIdx.x * 256 + threadIdx.x;
    if (i >= n) return;
    int r = g_row[i] + g_boff[blockIdx.x];
    g_row[i] = r;
    g_cur[i] = r;
}

// 4) payload = x * dinv (dinv = rsqrt(deg+1) from histogram)
__global__ void k_prep(const float* __restrict__ x, int n) {
    int i = blockIdx.x * blockDim.x + threadIdx.x;
    if (i >= n) return;
    float di = rsqrtf((float)(g_cnt[i] + 1));
    reinterpret_cast<float4*>(g_xs)[i] =
        make_float4(x[i * 3 + 0] * di, x[i * 3 + 1] * di, x[i * 3 + 2] * di, 0.f);
}

// 5) counting-sort placement: group src by dst, 4 edges/thread
__global__ void k_place(const int* __restrict__ edge_index, int E) {
    int i = blockIdx.x * blockDim.x + threadIdx.x;
    int e0 = i * 4;
    if (e0 >= E) return;
    const int* srcp = edge_index;
    const int* dstp = edge_index + E;
    if (e0 + 3 < E) {
        int4 s4 = *reinterpret_cast<const int4*>(srcp + e0);
        int4 d4 = *reinterpret_cast<const int4*>(dstp + e0);
        g_csr[atomicAdd(&g_cur[d4.x], 1)] = s4.x;
        g_csr[atomicAdd(&g_cur[d4.y], 1)] = s4.y;
        g_csr[atomicAdd(&g_cur[d4.z], 1)] = s4.z;
        g_csr[atomicAdd(&g_cur[d4.w], 1)] = s4.w;
    } else {
        for (int e = e0; e < E; e++)
            g_csr[atomicAdd(&g_cur[dstp[e]], 1)] = srcp[e];
    }
}

// 6) pull layer 1 + fused dense transform. Warp per node.
//    agg = dinv * (sum_{s in N(d)} xs[s] + xs[d]); h = relu(agg@W1+b1); t2s = (h@W2)*dinv
__global__ void k_pull1(const float* __restrict__ W1, const float* __restrict__ b1,
                        const float* __restrict__ W2, int n) {
    __shared__ float sW1[96], sb1[32], sW2[96];
    if (threadIdx.x < 96) sW1[threadIdx.x] = W1[threadIdx.x];
    if (threadIdx.x < 32) sb1[threadIdx.x] = b1[threadIdx.x];
    if (threadIdx.x >= 128 && threadIdx.x < 224) sW2[threadIdx.x - 128] = W2[threadIdx.x - 128];
    __syncthreads();
    int node = (blockIdx.x * blockDim.x + threadIdx.x) >> 5;
    int lane = threadIdx.x & 31;
    if (node >= n) return;
    int row = g_row[node];
    int cnt = g_cnt[node];
    float ax = 0.f, ay = 0.f, az = 0.f;
    for (int j = lane; j < cnt; j += 32) {
        int s = g_csr[row + j];
        float4 v = reinterpret_cast<const float4*>(g_xs)[s];
        ax += v.x; ay += v.y; az += v.z;
    }
#pragma unroll
    for (int off = 16; off; off >>= 1) {
        ax += __shfl_xor_sync(0xffffffffu, ax, off);
        ay += __shfl_xor_sync(0xffffffffu, ay, off);
        az += __shfl_xor_sync(0xffffffffu, az, off);
    }
    float4 self = reinterpret_cast<const float4*>(g_xs)[node];  // broadcast load
    float di = rsqrtf((float)(cnt + 1));
    ax = (ax + self.x) * di;
    ay = (ay + self.y) * di;
    az = (az + self.z) * di;
    // hidden unit per lane
    float h = fmaxf(ax * sW1[lane] + ay * sW1[32 + lane] + az * sW1[64 + lane] + sb1[lane], 0.f);
    float c0 = h * sW2[lane * 3 + 0];
    float c1 = h * sW2[lane * 3 + 1];
    float c2 = h * sW2[lane * 3 + 2];
#pragma unroll
    for (int off = 16; off; off >>= 1) {
        c0 += __shfl_xor_sync(0xffffffffu, c0, off);
        c1 += __shfl_xor_sync(0xffffffffu, c1, off);
        c2 += __shfl_xor_sync(0xffffffffu, c2, off);
    }
    if (lane == 0)
        reinterpret_cast<float4*>(g_t2s)[node] = make_float4(c0 * di, c1 * di, c2 * di, 0.f);
}

// 7) pull layer 2 + fused output epilogue. Warp per node.
__global__ void k_pull2(const float* __restrict__ b2, float* __restrict__ out, int n) {
    int node = (blockIdx.x * blockDim.x + threadIdx.x) >> 5;
    int lane = threadIdx.x & 31;
    if (node >= n) return;
    int row = g_row[node];
    int cnt = g_cnt[node];
    float ax = 0.f, ay = 0.f, az = 0.f;
    for (int j = lane; j < cnt; j += 32) {
        int s = g_csr[row + j];
        float4 v = reinterpret_cast<const float4*>(g_t2s)[s];
        ax += v.x; ay += v.y; az += v.z;
    }
#pragma unroll
    for (int off = 16; off; off >>= 1) {
        ax += __shfl_xor_sync(0xffffffffu, ax, off);
        ay += __shfl_xor_sync(0xffffffffu, ay, off);
        az += __shfl_xor_sync(0xffffffffu, az, off);
    }
    if (lane == 0) {
        float4 self = reinterpret_cast<const float4*>(g_t2s)[node];
        float di = rsqrtf((float)(cnt + 1));
        out[node * 3 + 0] = (ax + self.x) * di + __ldg(&b2[0]);
        out[node * 3 + 1] = (ay + self.y) * di + __ldg(&b2[1]);
        out[node * 3 + 2] = (az + self.z) * di + __ldg(&b2[2]);
    }
}

extern "C" void kernel_launch(void* const* d_in, const int* in_sizes, int n_in,
                              void* d_out, int out_size) {
    const float* x = (const float*)d_in[0];
    const int* edge_index = (const int*)d_in[1];  // int32 (JAX x64 disabled)
    const float* W1 = (const float*)d_in[2];
    const float* b1 = (const float*)d_in[3];
    const float* W2 = (const float*)d_in[4];
    const float* b2 = (const float*)d_in[5];
    float* out = (float*)d_out;

    int n = in_sizes[0] / 3;
    int E = in_sizes[1] / 2;

    const int B = 256;
    int nb = (n + 255) / 256;  // scan blocks (<= 512)

    k_zero<<<(n + B - 1) / B, B>>>(n);
    {
        int t = (E + 3) / 4;
        k_count<<<(t + B - 1) / B, B>>>(edge_index, E);
    }
    k_scan1<<<nb, 256>>>(n);
    k_scan2<<<1, 512>>>(nb);
    k_scan3<<<nb, 256>>>(n);
    k_prep<<<(n + B - 1) / B, B>>>(x, n);
    {
        int t = (E + 3) / 4;
        k_place<<<(t + B - 1) / B, B>>>(edge_index, E);
    }
    {
        long long threads = (long long)n * 32;
        unsigned grid = (unsigned)((threads + B - 1) / B);
        k_pull1<<<grid, B>>>(W1, b1, W2, n);
        k_pull2<<<grid, B>>>(b2, out, n);
    }
}

// round 14
// speedup vs baseline: 1.5417x; 1.5417x over previous
#include <cuda_runtime.h>
#include <cstdint>

// Problem-fixed maxima (N=100000, E=3200000 per reference setup_inputs).
#define MAXN 100000
#define MAXE 3200000

// Scratch (allocation-free contract: __device__ globals).
__device__ int g_cnt[MAXN];                        // in-degree (excluding self-loop)
__device__ __align__(16) float g_xs[MAXN * 4];     // x * dinv  (source-scaled payload)
__device__ __align__(16) float g_accx[MAXN * 4];   // layer-1 accumulator (pre dst-scale)
__device__ __align__(16) float g_t2s[MAXN * 4];    // t2 * dinv (source-scaled payload)
__device__ __align__(16) float g_acc2[MAXN * 4];   // layer-2 accumulator (pre dst-scale)
__device__ float g_dinv[MAXN];                     // rsqrt(deg)

__device__ __forceinline__ void red_add_v4(float* addr, float a, float b, float c, float d) {
    asm volatile("red.global.add.v4.f32 [%0], {%1, %2, %3, %4};"
                 :: "l"(addr), "f"(a), "f"(b), "f"(c), "f"(d) : "memory");
}

// 1) zero the degree histogram
__global__ void k_zero(int n) {
    int i = blockIdx.x * blockDim.x + threadIdx.x;
    if (i < n) g_cnt[i] = 0;
}

// 2) in-degree histogram, 4 edges/thread via int4 (read-only over dst stream)
__global__ void k_count(const int* __restrict__ edge_index, int E) {
    int i = blockIdx.x * blockDim.x + threadIdx.x;
    int e0 = i * 4;
    if (e0 >= E) return;
    const int* dstp = edge_index + E;
    if (e0 + 3 < E) {
        int4 d4 = *reinterpret_cast<const int4*>(dstp + e0);
        atomicAdd(&g_cnt[d4.x], 1);
        atomicAdd(&g_cnt[d4.y], 1);
        atomicAdd(&g_cnt[d4.z], 1);
        atomicAdd(&g_cnt[d4.w], 1);
    } else {
        for (int e = e0; e < E; e++) atomicAdd(&g_cnt[dstp[e]], 1);
    }
}

// 3) dinv = rsqrt(deg+1); payload xs = x * dinv; seed accx with payload (self-loop:
//    post-scale by dinv[d] later yields x[d] * dinv[d]^2).
__global__ void k_prep(const float* __restrict__ x, int n) {
    int i = blockIdx.x * blockDim.x + threadIdx.x;
    if (i >= n) return;
    float di = rsqrtf((float)(g_cnt[i] + 1));
    g_dinv[i] = di;
    float4 p = make_float4(x[i * 3 + 0] * di, x[i * 3 + 1] * di, x[i * 3 + 2] * di, 0.f);
    reinterpret_cast<float4*>(g_xs)[i] = p;
    reinterpret_cast<float4*>(g_accx)[i] = p;
}

// 4) layer-1 scatter: weightless copy-scatter, 4 edges/thread (front-batched MLP).
__global__ void k_scatter_x(const int* __restrict__ edge_index, int E) {
    int i = blockIdx.x * blockDim.x + threadIdx.x;
    int e0 = i * 4;
    if (e0 >= E) return;
    const int* srcp = edge_index;
    const int* dstp = edge_index + E;
    if (e0 + 3 < E) {
        int4 s4 = *reinterpret_cast<const int4*>(srcp + e0);
        int4 d4 = *reinterpret_cast<const int4*>(dstp + e0);
        const float4* xs = reinterpret_cast<const float4*>(g_xs);
        float4 v0 = xs[s4.x];
        float4 v1 = xs[s4.y];
        float4 v2 = xs[s4.z];
        float4 v3 = xs[s4.w];
        red_add_v4(&g_accx[d4.x * 4], v0.x, v0.y, v0.z, 0.f);
        red_add_v4(&g_accx[d4.y * 4], v1.x, v1.y, v1.z, 0.f);
        red_add_v4(&g_accx[d4.z * 4], v2.x, v2.y, v2.z, 0.f);
        red_add_v4(&g_accx[d4.w * 4], v3.x, v3.y, v3.z, 0.f);
    } else {
        for (int e = e0; e < E; e++) {
            float4 v = reinterpret_cast<const float4*>(g_xs)[srcp[e]];
            red_add_v4(&g_accx[dstp[e] * 4], v.x, v.y, v.z, 0.f);
        }
    }
}

// 5) fused: agg1 = accx * dinv (dst post-scale) -> h = relu(agg1 @ W1 + b1) -> t2 = h @ W2;
//    payload t2s = t2 * dinv; seed acc2 with t2s (self-loop).
__global__ void k_fused_transform(const float* __restrict__ W1, const float* __restrict__ b1,
                                  const float* __restrict__ W2, int n) {
    __shared__ float sW1[96];   // W1 [3, 32] row-major
    __shared__ float sb1[32];
    __shared__ float sW2[96];   // W2 [32, 3] row-major
    if (threadIdx.x < 96) sW1[threadIdx.x] = W1[threadIdx.x];
    if (threadIdx.x < 32) sb1[threadIdx.x] = b1[threadIdx.x];
    if (threadIdx.x >= 128 && threadIdx.x < 224) sW2[threadIdx.x - 128] = W2[threadIdx.x - 128];
    __syncthreads();
    int i = blockIdx.x * blockDim.x + threadIdx.x;
    if (i >= n) return;
    float di = g_dinv[i];
    float4 a = reinterpret_cast<const float4*>(g_accx)[i];
    a.x *= di; a.y *= di; a.z *= di;  // dst-side normalization of layer-1 aggregation
    float c0 = 0.f, c1 = 0.f, c2 = 0.f;
#pragma unroll
    for (int j = 0; j < 32; j++) {
        float h = fmaxf(a.x * sW1[j] + a.y * sW1[32 + j] + a.z * sW1[64 + j] + sb1[j], 0.f);
        c0 += h * sW2[j * 3 + 0];
        c1 += h * sW2[j * 3 + 1];
        c2 += h * sW2[j * 3 + 2];
    }
    float4 p = make_float4(c0 * di, c1 * di, c2 * di, 0.f);  // source-scaled payload
    reinterpret_cast<float4*>(g_t2s)[i] = p;
    reinterpret_cast<float4*>(g_acc2)[i] = p;                 // self-loop seed
}

// 6) layer-2 scatter: weightless copy-scatter, 4 edges/thread.
__global__ void k_scatter2(const int* __restrict__ edge_index, int E) {
    int i = blockIdx.x * blockDim.x + threadIdx.x;
    int e0 = i * 4;
    if (e0 >= E) return;
    const int* srcp = edge_index;
    const int* dstp = edge_index + E;
    if (e0 + 3 < E) {
        int4 s4 = *reinterpret_cast<const int4*>(srcp + e0);
        int4 d4 = *reinterpret_cast<const int4*>(dstp + e0);
        const float4* ts = reinterpret_cast<const float4*>(g_t2s);
        float4 v0 = ts[s4.x];
        float4 v1 = ts[s4.y];
        float4 v2 = ts[s4.z];
        float4 v3 = ts[s4.w];
        red_add_v4(&g_acc2[d4.x * 4], v0.x, v0.y, v0.z, 0.f);
        red_add_v4(&g_acc2[d4.y * 4], v1.x, v1.y, v1.z, 0.f);
        red_add_v4(&g_acc2[d4.z * 4], v2.x, v2.y, v2.z, 0.f);
        red_add_v4(&g_acc2[d4.w * 4], v3.x, v3.y, v3.z, 0.f);
    } else {
        for (int e = e0; e < E; e++) {
            float4 v = reinterpret_cast<const float4*>(g_t2s)[srcp[e]];
            red_add_v4(&g_acc2[dstp[e] * 4], v.x, v.y, v.z, 0.f);
        }
    }
}

// 7) out[i, :] = acc2[i, 0:3] * dinv[i] + b2 (dst post-scale + bias)
__global__ void k_out(const float* __restrict__ b2, float* __restrict__ out, int n) {
    int i = blockIdx.x * blockDim.x + threadIdx.x;
    if (i >= n) return;
    float di = g_dinv[i];
    float4 a = reinterpret_cast<const float4*>(g_acc2)[i];
    out[i * 3 + 0] = a.x * di + __ldg(&b2[0]);
    out[i * 3 + 1] = a.y * di + __ldg(&b2[1]);
    out[i * 3 + 2] = a.z * di + __ldg(&b2[2]);
}

extern "C" void kernel_launch(void* const* d_in, const int* in_sizes, int n_in,
                              void* d_out, int out_size) {
    const float* x = (const float*)d_in[0];
    const int* edge_index = (const int*)d_in[1];  // int32 (JAX x64 disabled)
    const float* W1 = (const float*)d_in[2];
    const float* b1 = (const float*)d_in[3];
    const float* W2 = (const float*)d_in[4];
    const float* b2 = (const float*)d_in[5];
    float* out = (float*)d_out;

    int n = in_sizes[0] / 3;
    int E = in_sizes[1] / 2;

    const int B = 256;
    int tE4 = ((E + 3) / 4 + B - 1) / B;

    k_zero<<<(n + B - 1) / B, B>>>(n);
    k_count<<<tE4, B>>>(edge_index, E);
    k_prep<<<(n + B - 1) / B, B>>>(x, n);
    k_scatter_x<<<tE4, B>>>(edge_index, E);
    k_fused_transform<<<(n + B - 1) / B, B>>>(W1, b1, W2, n);
    k_scatter2<<<tE4, B>>>(edge_index, E);
    k_out<<<(n + B - 1) / B, B>>>(b2, out, n);
}